// round 15
// baseline (speedup 1.0000x reference)
#include <cuda_runtime.h>
#include <cuda_fp16.h>
#include <mma.h>
#include <cstddef>

using namespace nvcuda;

#define NN 50000
#define NE_MAX 800000
#define FIN 128
#define H1 100
#define H2 200
#define FOUT 16
#define HP 128           // padded payload row: 128 halves = 256 B (2 aligned lines)
#define C4_H1 (H1 / 4)   // 25 real 4-half chunks per row

// -------- scratch (static device globals; no allocation) --------
__device__ __align__(16) int    g_deg[NN];
__device__ __align__(16) float  g_dis[NN];
__device__ __align__(16) int    g_off[NN];
__device__ __align__(16) int    g_cur[NN];
__device__               int    g_total;
__device__ __align__(16) int    g_src[NE_MAX];
__device__ __align__(16) __half g_w1h[128 * 120];        // W1 fp16, N 100->120
__device__ __align__(16) __half g_w2h[128 * 208];        // W2 fp16, K 100->128, N 200->208
__device__ __align__(16) __half g_wfh[208 * FOUT];       // Wfc fp16, K 200->208
__device__ __align__(256) __half g_y1h[(size_t)NN * HP]; // fp16 payload 1, 256B rows
__device__ __align__(256) __half g_y2h[(size_t)NN * HP]; // fp16 payload 2
__device__ __align__(256) __half g_s2h[(size_t)NN * HP]; // fp16 dense2 input

// ================= degree / CSR build =================
__global__ void k_count_deg(const int* __restrict__ col, int nE) {
    int q = blockIdx.x * blockDim.x + threadIdx.x;
    int nQ = nE >> 2;
    if (q < nQ) {
        int4 c = *(const int4*)(col + q * 4);
        if ((unsigned)c.x < (unsigned)NN) atomicAdd(&g_deg[c.x], 1);
        if ((unsigned)c.y < (unsigned)NN) atomicAdd(&g_deg[c.y], 1);
        if ((unsigned)c.z < (unsigned)NN) atomicAdd(&g_deg[c.z], 1);
        if ((unsigned)c.w < (unsigned)NN) atomicAdd(&g_deg[c.w], 1);
    } else if (q == nQ) {
        for (int e = nQ * 4; e < nE; e++) {
            int t = col[e];
            if ((unsigned)t < (unsigned)NN) atomicAdd(&g_deg[t], 1);
        }
    }
}

__global__ void k_assign(int n) {
    int i = blockIdx.x * blockDim.x + threadIdx.x;
    if (i >= n) return;
    int d = g_deg[i];
    g_dis[i] = rsqrtf((float)(d + 1));
    int off = atomicAdd(&g_total, d);
    g_off[i] = off;
    g_cur[i] = off;
}

__global__ void k_fill(const int* __restrict__ row, const int* __restrict__ col, int nE) {
    int q = blockIdx.x * blockDim.x + threadIdx.x;
    int nQ = nE >> 2;
    if (q < nQ) {
        int4 r = *(const int4*)(row + q * 4);
        int4 c = *(const int4*)(col + q * 4);
        int s0 = -1, s1 = -1, s2 = -1, s3 = -1;
        if ((unsigned)c.x < (unsigned)NN && (unsigned)r.x < (unsigned)NN) s0 = atomicAdd(&g_cur[c.x], 1);
        if ((unsigned)c.y < (unsigned)NN && (unsigned)r.y < (unsigned)NN) s1 = atomicAdd(&g_cur[c.y], 1);
        if ((unsigned)c.z < (unsigned)NN && (unsigned)r.z < (unsigned)NN) s2 = atomicAdd(&g_cur[c.z], 1);
        if ((unsigned)c.w < (unsigned)NN && (unsigned)r.w < (unsigned)NN) s3 = atomicAdd(&g_cur[c.w], 1);
        if (s0 >= 0) g_src[s0] = r.x;
        if (s1 >= 0) g_src[s1] = r.y;
        if (s2 >= 0) g_src[s2] = r.z;
        if (s3 >= 0) g_src[s3] = r.w;
    } else if (q == nQ) {
        for (int e = nQ * 4; e < nE; e++) {
            int rr = row[e], t = col[e];
            if ((unsigned)rr >= (unsigned)NN || (unsigned)t >= (unsigned)NN) continue;
            int slot = atomicAdd(&g_cur[t], 1);
            g_src[slot] = rr;
        }
    }
}

// ================= single fused weight convert =================
#define W1_ELEMS (128 * 120)
#define W2_ELEMS (128 * 208)
#define WF_ELEMS (208 * FOUT)
__global__ void k_conv_w(const float* __restrict__ W1, const float* __restrict__ W2,
                         const float* __restrict__ Wfc) {
    int idx = blockIdx.x * blockDim.x + threadIdx.x;
    if (idx < W1_ELEMS) {
        int k = idx / 120, j = idx - k * 120;
        g_w1h[idx] = __float2half((j < H1) ? W1[(size_t)k * H1 + j] : 0.f);
    } else if (idx < W1_ELEMS + W2_ELEMS) {
        int t = idx - W1_ELEMS;
        int k = t / 208, j = t - k * 208;
        g_w2h[t] = __float2half((k < H1 && j < H2) ? W2[(size_t)k * H2 + j] : 0.f);
    } else if (idx < W1_ELEMS + W2_ELEMS + WF_ELEMS) {
        int t = idx - W1_ELEMS - W2_ELEMS;
        int k = t / FOUT, j = t - k * FOUT;
        g_wfh[t] = __float2half((k < H2) ? Wfc[(size_t)k * FOUT + j] : 0.f);
    }
}

// ================= dense1 via WMMA (fp16 in, fp32 acc, fp16 out scaled by dis) =================
// Output rows padded to HP=128 halves; cols 100..127 written zero.
__global__ void __launch_bounds__(128)
k_dense1_wmma(const float* __restrict__ x, __half* __restrict__ y1h, int nRows) {
    __shared__ __align__(16) __half s_x[64 * 128];   // 16 KB
    __shared__ __align__(16) __half s_w[128 * 120];  // 30 KB

    int tid  = threadIdx.x;
    int warp = tid >> 5;
    int lane = tid & 31;
    int r0   = blockIdx.x * 64;

    const float4* x4 = (const float4*)x;
    for (int i = tid; i < 64 * 32; i += 128) {
        int r = i >> 5, c = i & 31;
        int gr = r0 + r;
        float4 v = (gr < nRows) ? x4[(size_t)gr * 32 + c] : make_float4(0.f, 0.f, 0.f, 0.f);
        __half2 h0 = __floats2half2_rn(v.x, v.y);
        __half2 h1 = __floats2half2_rn(v.z, v.w);
        uint2 u = make_uint2(*(unsigned*)&h0, *(unsigned*)&h1);
        *(uint2*)&s_x[r * 128 + c * 4] = u;
    }
    {
        const int4* wsrc = (const int4*)g_w1h;
        int4* wdst = (int4*)s_w;
        for (int i = tid; i < 1920; i += 128) wdst[i] = wsrc[i];
    }
    __syncthreads();

    wmma::fragment<wmma::matrix_a, 16, 16, 16, __half, wmma::row_major> afrag[8];
#pragma unroll
    for (int k = 0; k < 8; k++)
        wmma::load_matrix_sync(afrag[k], &s_x[(warp * 16) * 128 + k * 16], 128);
    __syncthreads();

    float* s_c = (float*)s_x + warp * 256;

    for (int n = 0; n < 7; n++) {   // covers cols 0..111
        wmma::fragment<wmma::accumulator, 16, 16, 16, float> acc;
        wmma::fill_fragment(acc, 0.f);
#pragma unroll
        for (int k = 0; k < 8; k++) {
            wmma::fragment<wmma::matrix_b, 16, 16, 16, __half, wmma::row_major> bfrag;
            wmma::load_matrix_sync(bfrag, &s_w[(k * 16) * 120 + n * 16], 120);
            wmma::mma_sync(acc, afrag[k], bfrag, acc);
        }
        wmma::store_matrix_sync(s_c, acc, 16, wmma::mem_row_major);
        __syncwarp();
        for (int i = lane; i < 128; i += 32) {
            int r = i >> 3, p = i & 7;
            int gr = r0 + warp * 16 + r;
            int gc = n * 16 + p * 2;
            if (gr < nRows) {
                float v0 = 0.f, v1 = 0.f;
                if (gc < H1) {   // H1 even; pair fully in- or out-of-range
                    float d = g_dis[gr];
                    v0 = s_c[r * 16 + p * 2]     * d;
                    v1 = s_c[r * 16 + p * 2 + 1] * d;
                }
                __half2 h = __floats2half2_rn(v0, v1);
                *(unsigned*)&y1h[(size_t)gr * HP + gc] = *(unsigned*)&h;
            }
        }
        __syncwarp();
    }
    // zero pad cols 112..127 (4 uint2 chunks per row)
    for (int i = lane; i < 64; i += 32) {
        int r = i >> 2, c = 28 + (i & 3);
        int gr = r0 + warp * 16 + r;
        if (gr < nRows)
            *(uint2*)&y1h[(size_t)gr * HP + c * 4] = make_uint2(0u, 0u);
    }
}

// ================= dense2 + FC fused via WMMA =================
// A rows are HP=128-padded (pad already zero). K2 = 128.
__global__ void __launch_bounds__(128)
k_dense2_fc_wmma(const __half* __restrict__ s2h, const float* __restrict__ b2,
                 const float* __restrict__ bfc, float* __restrict__ out, int nRows) {
    __shared__ __align__(16) __half s_a[64 * 128];    // 16 KB
    __shared__ __align__(16) __half s_r[64 * 208];    // 26 KB (relu mid, fp16)
    __shared__ __align__(16) float  s_c4[4 * 256];    // 4 KB epilogue scratch

    int tid  = threadIdx.x;
    int warp = tid >> 5;
    int lane = tid & 31;
    int r0   = blockIdx.x * 64;

    // load s2h tile: 32 uint2 chunks per row (pad cols already zero in payload)
    for (int i = tid; i < 64 * 32; i += 128) {
        int r = i >> 5, c = i & 31;
        int gr = r0 + r;
        uint2 u = make_uint2(0u, 0u);
        if (gr < nRows)
            u = __ldg((const uint2*)(s2h + (size_t)gr * HP) + c);
        *(uint2*)&s_a[r * 128 + c * 4] = u;
    }
    __syncthreads();

    wmma::fragment<wmma::matrix_a, 16, 16, 16, __half, wmma::row_major> afrag[8];
#pragma unroll
    for (int k = 0; k < 8; k++)
        wmma::load_matrix_sync(afrag[k], &s_a[(warp * 16) * 128 + k * 16], 128);

    float* s_c = s_c4 + warp * 256;

    // ---- stage 1: 13 n-tiles of relu(s2h@W2+b2) -> s_r (fp16) ----
    for (int n = 0; n < 13; n++) {
        wmma::fragment<wmma::accumulator, 16, 16, 16, float> acc;
        wmma::fill_fragment(acc, 0.f);
#pragma unroll
        for (int k = 0; k < 8; k++) {
            wmma::fragment<wmma::matrix_b, 16, 16, 16, __half, wmma::row_major> bfrag;
            wmma::load_matrix_sync(bfrag, &g_w2h[(k * 16) * 208 + n * 16], 208);
            wmma::mma_sync(acc, afrag[k], bfrag, acc);
        }
        wmma::store_matrix_sync(s_c, acc, 16, wmma::mem_row_major);
        __syncwarp();
        for (int i = lane; i < 128; i += 32) {   // 16 rows x 8 pairs
            int r = i >> 3, p = i & 7;
            int gc = n * 16 + p * 2;
            float v0 = 0.f, v1 = 0.f;
            if (gc < H2) {
                v0 = fmaxf(s_c[r * 16 + p * 2]     + __ldg(&b2[gc]),     0.f);
                v1 = fmaxf(s_c[r * 16 + p * 2 + 1] + __ldg(&b2[gc + 1]), 0.f);
            }
            __half2 h = __floats2half2_rn(v0, v1);
            *(unsigned*)&s_r[(warp * 16 + r) * 208 + gc] = *(unsigned*)&h;
        }
        __syncwarp();
    }
    __syncthreads();

    // ---- stage 2: out = s_r @ Wfc + bfc ----
    {
        wmma::fragment<wmma::accumulator, 16, 16, 16, float> acc;
        wmma::fill_fragment(acc, 0.f);
#pragma unroll
        for (int k = 0; k < 13; k++) {
            wmma::fragment<wmma::matrix_a, 16, 16, 16, __half, wmma::row_major> a2;
            wmma::load_matrix_sync(a2, &s_r[(warp * 16) * 208 + k * 16], 208);
            wmma::fragment<wmma::matrix_b, 16, 16, 16, __half, wmma::row_major> bfrag;
            wmma::load_matrix_sync(bfrag, &g_wfh[(k * 16) * FOUT], FOUT);
            wmma::mma_sync(acc, a2, bfrag, acc);
        }
        wmma::store_matrix_sync(s_c, acc, 16, wmma::mem_row_major);
        __syncwarp();
        for (int i = lane; i < 256; i += 32) {
            int r = i >> 4, c = i & 15;
            int gr = r0 + warp * 16 + r;
            if (gr < nRows)
                out[(size_t)gr * FOUT + c] = s_c[r * 16 + c] + __ldg(&bfc[c]);
        }
    }
}

// ================= CSR gather aggregation, fp16 256B-aligned rows =================
// All 32 lanes active: lane = one uint2 (4 halves); rows are exactly 2 aligned lines.
// MODE 1: out = d * relu(d * acc + bias)   MODE 2: out = d * acc
template <int MODE>
__global__ void __launch_bounds__(256)
k_gather_h(const __half* __restrict__ y, const float* __restrict__ bias,
           __half* __restrict__ outh, int nN) {
    int node = blockIdx.x * blockDim.y + threadIdx.y;
    if (node >= nN) return;
    int lane  = threadIdx.x;
    int start = g_off[node];
    int cnt   = g_deg[node];

    float4 acc;
    {
        uint2 u = __ldg((const uint2*)(y + (size_t)node * HP) + lane);
        float2 f0 = __half22float2(*(const __half2*)&u.x);
        float2 f1 = __half22float2(*(const __half2*)&u.y);
        acc = make_float4(f0.x, f0.y, f1.x, f1.y);
    }

    int j = 0;
    for (; j + 8 <= cnt; j += 8) {
        int rr[8];
#pragma unroll
        for (int u = 0; u < 8; u++) rr[u] = __ldg(&g_src[start + j + u]);
#pragma unroll
        for (int u = 0; u < 8; u++) {
            uint2 w = __ldg((const uint2*)(y + (size_t)rr[u] * HP) + lane);
            float2 f0 = __half22float2(*(const __half2*)&w.x);
            float2 f1 = __half22float2(*(const __half2*)&w.y);
            acc.x += f0.x; acc.y += f0.y; acc.z += f1.x; acc.w += f1.y;
        }
    }
    if (j + 4 <= cnt) {
        int rr[4];
#pragma unroll
        for (int u = 0; u < 4; u++) rr[u] = __ldg(&g_src[start + j + u]);
#pragma unroll
        for (int u = 0; u < 4; u++) {
            uint2 w = __ldg((const uint2*)(y + (size_t)rr[u] * HP) + lane);
            float2 f0 = __half22float2(*(const __half2*)&w.x);
            float2 f1 = __half22float2(*(const __half2*)&w.y);
            acc.x += f0.x; acc.y += f0.y; acc.z += f1.x; acc.w += f1.y;
        }
        j += 4;
    }
    for (; j < cnt; j++) {
        int r = __ldg(&g_src[start + j]);
        uint2 w = __ldg((const uint2*)(y + (size_t)r * HP) + lane);
        float2 f0 = __half22float2(*(const __half2*)&w.x);
        float2 f1 = __half22float2(*(const __half2*)&w.y);
        acc.x += f0.x; acc.y += f0.y; acc.z += f1.x; acc.w += f1.y;
    }

    {
        float d = g_dis[node];
        float o0, o1, o2, o3;
        if (MODE == 1) {
            float4 b = (lane < C4_H1) ? *(const float4*)&bias[lane * 4]
                                      : make_float4(0.f, 0.f, 0.f, 0.f);
            o0 = d * fmaxf(fmaf(d, acc.x, b.x), 0.f);
            o1 = d * fmaxf(fmaf(d, acc.y, b.y), 0.f);
            o2 = d * fmaxf(fmaf(d, acc.z, b.z), 0.f);
            o3 = d * fmaxf(fmaf(d, acc.w, b.w), 0.f);
        } else {
            o0 = d * acc.x; o1 = d * acc.y; o2 = d * acc.z; o3 = d * acc.w;
        }
        __half2 h0 = __floats2half2_rn(o0, o1);
        __half2 h1 = __floats2half2_rn(o2, o3);
        uint2 u;
        u.x = *(const unsigned*)&h0;
        u.y = *(const unsigned*)&h1;
        ((uint2*)(outh + (size_t)node * HP))[lane] = u;
    }
}

// ================= launch =================
extern "C" void kernel_launch(void* const* d_in, const int* in_sizes, int n_in,
                              void* d_out, int out_size) {
    const float* x   = (const float*)d_in[0];
    const int*   ei  = (const int*)d_in[1];
    const float* W1  = (const float*)d_in[2];
    const float* b1  = (const float*)d_in[3];
    const float* W2  = (const float*)d_in[4];
    const float* b2  = (const float*)d_in[5];
    const float* Wfc = (const float*)d_in[6];
    const float* bfc = (const float*)d_in[7];
    float*       out = (float*)d_out;

    int nN = in_sizes[0] / FIN;
    int nE = in_sizes[1] / 2;
    const int* rowI = ei;
    const int* colI = ei + nE;

    __half *p_y1h, *p_y2h, *p_s2h;
    int    *p_deg, *p_total;
    cudaGetSymbolAddress((void**)&p_y1h,  g_y1h);
    cudaGetSymbolAddress((void**)&p_y2h,  g_y2h);
    cudaGetSymbolAddress((void**)&p_s2h,  g_s2h);
    cudaGetSymbolAddress((void**)&p_deg,  g_deg);
    cudaGetSymbolAddress((void**)&p_total, g_total);

    // --- degree + CSR build ---
    cudaMemsetAsync(p_deg, 0, (size_t)nN * sizeof(int));
    cudaMemsetAsync(p_total, 0, sizeof(int));
    {
        int nQ = nE / 4 + 1;
        k_count_deg<<<(nQ + 255) / 256, 256>>>(colI, nE);
        k_assign   <<<(nN + 255) / 256, 256>>>(nN);
        k_fill     <<<(nQ + 255) / 256, 256>>>(rowI, colI, nE);
    }

    // --- fused weight converts ---
    k_conv_w<<<(W1_ELEMS + W2_ELEMS + WF_ELEMS + 255) / 256, 256>>>(W1, W2, Wfc);

    // --- layer 1 (WMMA): y1h = fp16( d_r ⊙ (x @ W1) ), 256B rows ---
    k_dense1_wmma<<<(nN + 63) / 64, 128>>>(x, p_y1h, nN);

    // --- agg1 + mid fused: y2h = fp16( d ⊙ relu(d ⊙ (y1_self + Σ y1[src]) + b1) ) ---
    k_gather_h<1><<<(nN + 7) / 8, dim3(32, 8)>>>(p_y1h, b1, p_y2h, nN);

    // --- agg2 (commuted before GEMM): s2h = fp16( d ⊙ (y2_self + Σ y2[src]) ) ---
    k_gather_h<2><<<(nN + 7) / 8, dim3(32, 8)>>>(p_y2h, nullptr, p_s2h, nN);

    // --- layer 2 + FC fused (WMMA): out = relu(s2h @ W2 + b2) @ Wfc + bfc ---
    k_dense2_fc_wmma<<<(nN + 63) / 64, 128>>>(p_s2h, b2, bfc, out, nN);
}

// round 17
// speedup vs baseline: 1.0707x; 1.0707x over previous
#include <cuda_runtime.h>
#include <cuda_fp16.h>
#include <mma.h>
#include <cstddef>

using namespace nvcuda;

#define NN 50000
#define NE_MAX 800000
#define FIN 128
#define H1 100
#define H2 200
#define FOUT 16
#define C4_H1 (H1 / 4)   // 25 4-half chunks per row

// -------- scratch (static device globals; no allocation) --------
__device__ __align__(16) int    g_deg[NN];
__device__ __align__(16) float  g_dis[NN];
__device__ __align__(16) int    g_off[NN];
__device__ __align__(16) int    g_cur[NN];
__device__               int    g_total;
__device__ __align__(16) int    g_src[NE_MAX];
__device__ __align__(16) __half g_w1h[128 * 120];        // W1 fp16, N 100->120
__device__ __align__(16) __half g_w2h[112 * 208];        // W2 fp16, K 100->112, N 200->208
__device__ __align__(16) __half g_wfh[208 * FOUT];       // Wfc fp16, K 200->208
__device__ __align__(16) __half g_y1h[(size_t)NN * H1];  // fp16 gather payload 1
__device__ __align__(16) __half g_y2h[(size_t)NN * H1];  // fp16 gather payload 2
__device__ __align__(16) __half g_s2h[(size_t)NN * H1];  // fp16 dense2 input

// ================= fused degree-count + weight-convert =================
#define W1_ELEMS (128 * 120)
#define W2_ELEMS (112 * 208)
#define WF_ELEMS (208 * FOUT)
#define WCONV_ELEMS (W1_ELEMS + W2_ELEMS + WF_ELEMS)

__global__ void k_count_conv(const int* __restrict__ col, int nE, int nQB,
                             const float* __restrict__ W1, const float* __restrict__ W2,
                             const float* __restrict__ Wfc) {
    int tid = threadIdx.x;
    if ((int)blockIdx.x < nQB) {
        // degree count: 4 edges per thread
        int q = blockIdx.x * blockDim.x + tid;
        int nQ = nE >> 2;
        if (q < nQ) {
            int4 c = *(const int4*)(col + q * 4);
            if ((unsigned)c.x < (unsigned)NN) atomicAdd(&g_deg[c.x], 1);
            if ((unsigned)c.y < (unsigned)NN) atomicAdd(&g_deg[c.y], 1);
            if ((unsigned)c.z < (unsigned)NN) atomicAdd(&g_deg[c.z], 1);
            if ((unsigned)c.w < (unsigned)NN) atomicAdd(&g_deg[c.w], 1);
        } else if (q == nQ) {
            for (int e = nQ * 4; e < nE; e++) {
                int t = col[e];
                if ((unsigned)t < (unsigned)NN) atomicAdd(&g_deg[t], 1);
            }
        }
    } else {
        // weight convert
        int idx = (blockIdx.x - nQB) * blockDim.x + tid;
        if (idx < W1_ELEMS) {
            int k = idx / 120, j = idx - k * 120;
            g_w1h[idx] = __float2half((j < H1) ? W1[(size_t)k * H1 + j] : 0.f);
        } else if (idx < W1_ELEMS + W2_ELEMS) {
            int t = idx - W1_ELEMS;
            int k = t / 208, j = t - k * 208;
            g_w2h[t] = __float2half((k < H1 && j < H2) ? W2[(size_t)k * H2 + j] : 0.f);
        } else if (idx < WCONV_ELEMS) {
            int t = idx - W1_ELEMS - W2_ELEMS;
            int k = t / FOUT, j = t - k * FOUT;
            g_wfh[t] = __float2half((k < H2) ? Wfc[(size_t)k * FOUT + j] : 0.f);
        }
    }
}

__global__ void k_assign(int n) {
    int i = blockIdx.x * blockDim.x + threadIdx.x;
    if (i >= n) return;
    int d = g_deg[i];
    g_dis[i] = rsqrtf((float)(d + 1));
    int off = atomicAdd(&g_total, d);
    g_off[i] = off;
    g_cur[i] = off;
}

__global__ void k_fill(const int* __restrict__ row, const int* __restrict__ col, int nE) {
    int q = blockIdx.x * blockDim.x + threadIdx.x;
    int nQ = nE >> 2;
    if (q < nQ) {
        int4 r = *(const int4*)(row + q * 4);
        int4 c = *(const int4*)(col + q * 4);
        int s0 = -1, s1 = -1, s2 = -1, s3 = -1;
        if ((unsigned)c.x < (unsigned)NN && (unsigned)r.x < (unsigned)NN) s0 = atomicAdd(&g_cur[c.x], 1);
        if ((unsigned)c.y < (unsigned)NN && (unsigned)r.y < (unsigned)NN) s1 = atomicAdd(&g_cur[c.y], 1);
        if ((unsigned)c.z < (unsigned)NN && (unsigned)r.z < (unsigned)NN) s2 = atomicAdd(&g_cur[c.z], 1);
        if ((unsigned)c.w < (unsigned)NN && (unsigned)r.w < (unsigned)NN) s3 = atomicAdd(&g_cur[c.w], 1);
        if (s0 >= 0) g_src[s0] = r.x;
        if (s1 >= 0) g_src[s1] = r.y;
        if (s2 >= 0) g_src[s2] = r.z;
        if (s3 >= 0) g_src[s3] = r.w;
    } else if (q == nQ) {
        for (int e = nQ * 4; e < nE; e++) {
            int rr = row[e], t = col[e];
            if ((unsigned)rr >= (unsigned)NN || (unsigned)t >= (unsigned)NN) continue;
            int slot = atomicAdd(&g_cur[t], 1);
            g_src[slot] = rr;
        }
    }
}

// ================= dense1 via WMMA (B fragments straight from global) =================
__global__ void __launch_bounds__(128)
k_dense1_wmma(const float* __restrict__ x, __half* __restrict__ y1h, int nRows) {
    __shared__ __align__(16) __half s_x[64 * 128];   // 16 KB (reused as epilogue scratch)

    int tid  = threadIdx.x;
    int warp = tid >> 5;
    int lane = tid & 31;
    int r0   = blockIdx.x * 64;

    const float4* x4 = (const float4*)x;
    for (int i = tid; i < 64 * 32; i += 128) {
        int r = i >> 5, c = i & 31;
        int gr = r0 + r;
        float4 v = (gr < nRows) ? x4[(size_t)gr * 32 + c] : make_float4(0.f, 0.f, 0.f, 0.f);
        __half2 h0 = __floats2half2_rn(v.x, v.y);
        __half2 h1 = __floats2half2_rn(v.z, v.w);
        uint2 u = make_uint2(*(unsigned*)&h0, *(unsigned*)&h1);
        *(uint2*)&s_x[r * 128 + c * 4] = u;
    }
    __syncthreads();

    wmma::fragment<wmma::matrix_a, 16, 16, 16, __half, wmma::row_major> afrag[8];
#pragma unroll
    for (int k = 0; k < 8; k++)
        wmma::load_matrix_sync(afrag[k], &s_x[(warp * 16) * 128 + k * 16], 128);
    __syncthreads();   // s_x now reusable as epilogue scratch

    float* s_c = (float*)s_x + warp * 256;

    for (int n = 0; n < 7; n++) {
        wmma::fragment<wmma::accumulator, 16, 16, 16, float> acc;
        wmma::fill_fragment(acc, 0.f);
#pragma unroll
        for (int k = 0; k < 8; k++) {
            wmma::fragment<wmma::matrix_b, 16, 16, 16, __half, wmma::row_major> bfrag;
            wmma::load_matrix_sync(bfrag, &g_w1h[(k * 16) * 120 + n * 16], 120);
            wmma::mma_sync(acc, afrag[k], bfrag, acc);
        }
        wmma::store_matrix_sync(s_c, acc, 16, wmma::mem_row_major);
        __syncwarp();
        for (int i = lane; i < 128; i += 32) {
            int r = i >> 3, p = i & 7;
            int gr = r0 + warp * 16 + r;
            int gc = n * 16 + p * 2;
            if (gr < nRows && gc < H1) {
                float d = g_dis[gr];
                __half2 h = __floats2half2_rn(s_c[r * 16 + p * 2] * d,
                                              s_c[r * 16 + p * 2 + 1] * d);
                *(unsigned*)&y1h[(size_t)gr * H1 + gc] = *(unsigned*)&h;
            }
        }
        __syncwarp();
    }
}

// ================= dense2 + FC fused via WMMA =================
__global__ void __launch_bounds__(128)
k_dense2_fc_wmma(const __half* __restrict__ s2h, const float* __restrict__ b2,
                 const float* __restrict__ bfc, float* __restrict__ out, int nRows) {
    __shared__ __align__(16) __half s_a[64 * 112];    // 14 KB
    __shared__ __align__(16) __half s_r[64 * 208];    // 26 KB (relu mid, fp16)
    __shared__ __align__(16) float  s_c4[4 * 256];    // 4 KB epilogue scratch

    int tid  = threadIdx.x;
    int warp = tid >> 5;
    int lane = tid & 31;
    int r0   = blockIdx.x * 64;

    for (int i = tid; i < 64 * 28; i += 128) {
        int r = i / 28, c = i - r * 28;
        int gr = r0 + r;
        uint2 u = make_uint2(0u, 0u);
        if (gr < nRows && c < 25)
            u = __ldg((const uint2*)(s2h + (size_t)gr * H1) + c);
        *(uint2*)&s_a[r * 112 + c * 4] = u;
    }
    __syncthreads();

    wmma::fragment<wmma::matrix_a, 16, 16, 16, __half, wmma::row_major> afrag[7];
#pragma unroll
    for (int k = 0; k < 7; k++)
        wmma::load_matrix_sync(afrag[k], &s_a[(warp * 16) * 112 + k * 16], 112);

    float* s_c = s_c4 + warp * 256;

    // ---- stage 1: 13 n-tiles of relu(s2h@W2+b2) -> s_r (fp16) ----
    for (int n = 0; n < 13; n++) {
        wmma::fragment<wmma::accumulator, 16, 16, 16, float> acc;
        wmma::fill_fragment(acc, 0.f);
#pragma unroll
        for (int k = 0; k < 7; k++) {
            wmma::fragment<wmma::matrix_b, 16, 16, 16, __half, wmma::row_major> bfrag;
            wmma::load_matrix_sync(bfrag, &g_w2h[(k * 16) * 208 + n * 16], 208);
            wmma::mma_sync(acc, afrag[k], bfrag, acc);
        }
        wmma::store_matrix_sync(s_c, acc, 16, wmma::mem_row_major);
        __syncwarp();
        for (int i = lane; i < 128; i += 32) {
            int r = i >> 3, p = i & 7;
            int gc = n * 16 + p * 2;
            float v0 = 0.f, v1 = 0.f;
            if (gc < H2) {
                v0 = fmaxf(s_c[r * 16 + p * 2]     + __ldg(&b2[gc]),     0.f);
                v1 = fmaxf(s_c[r * 16 + p * 2 + 1] + __ldg(&b2[gc + 1]), 0.f);
            }
            __half2 h = __floats2half2_rn(v0, v1);
            *(unsigned*)&s_r[(warp * 16 + r) * 208 + gc] = *(unsigned*)&h;
        }
        __syncwarp();
    }
    __syncthreads();

    // ---- stage 2: out = s_r @ Wfc + bfc ----
    {
        wmma::fragment<wmma::accumulator, 16, 16, 16, float> acc;
        wmma::fill_fragment(acc, 0.f);
#pragma unroll
        for (int k = 0; k < 13; k++) {
            wmma::fragment<wmma::matrix_a, 16, 16, 16, __half, wmma::row_major> a2;
            wmma::load_matrix_sync(a2, &s_r[(warp * 16) * 208 + k * 16], 208);
            wmma::fragment<wmma::matrix_b, 16, 16, 16, __half, wmma::row_major> bfrag;
            wmma::load_matrix_sync(bfrag, &g_wfh[(k * 16) * FOUT], FOUT);
            wmma::mma_sync(acc, a2, bfrag, acc);
        }
        wmma::store_matrix_sync(s_c, acc, 16, wmma::mem_row_major);
        __syncwarp();
        for (int i = lane; i < 256; i += 32) {
            int r = i >> 4, c = i & 15;
            int gr = r0 + warp * 16 + r;
            if (gr < nRows)
                out[(size_t)gr * FOUT + c] = s_c[r * 16 + c] + __ldg(&bfc[c]);
        }
    }
}

// ================= CSR gather aggregation, fp16 payload =================
// MODE 1: out(fp16) = d * relu(d * acc + bias)
// MODE 2: out(fp16) = d * acc
template <int C4, int MODE>
__global__ void __launch_bounds__(256)
k_gather_h(const __half* __restrict__ y, const float* __restrict__ bias,
           __half* __restrict__ outh, int nN) {
    int node = blockIdx.x * blockDim.y + threadIdx.y;
    if (node >= nN) return;
    int lane  = threadIdx.x;
    int start = g_off[node];
    int cnt   = g_deg[node];
    bool act  = (lane < C4);

    float4 acc = make_float4(0.f, 0.f, 0.f, 0.f);
    if (act) {
        uint2 u = __ldg((const uint2*)(y + (size_t)node * H1) + lane);
        float2 f0 = __half22float2(*(const __half2*)&u.x);
        float2 f1 = __half22float2(*(const __half2*)&u.y);
        acc = make_float4(f0.x, f0.y, f1.x, f1.y);
    }

    int j = 0;
    for (; j + 8 <= cnt; j += 8) {
        int rr[8];
#pragma unroll
        for (int u = 0; u < 8; u++) rr[u] = __ldg(&g_src[start + j + u]);
#pragma unroll
        for (int u = 0; u < 8; u++) {
            if (act) {
                uint2 w = __ldg((const uint2*)(y + (size_t)rr[u] * H1) + lane);
                float2 f0 = __half22float2(*(const __half2*)&w.x);
                float2 f1 = __half22float2(*(const __half2*)&w.y);
                acc.x += f0.x; acc.y += f0.y; acc.z += f1.x; acc.w += f1.y;
            }
        }
    }
    if (j + 4 <= cnt) {
        int rr[4];
#pragma unroll
        for (int u = 0; u < 4; u++) rr[u] = __ldg(&g_src[start + j + u]);
#pragma unroll
        for (int u = 0; u < 4; u++) {
            if (act) {
                uint2 w = __ldg((const uint2*)(y + (size_t)rr[u] * H1) + lane);
                float2 f0 = __half22float2(*(const __half2*)&w.x);
                float2 f1 = __half22float2(*(const __half2*)&w.y);
                acc.x += f0.x; acc.y += f0.y; acc.z += f1.x; acc.w += f1.y;
            }
        }
        j += 4;
    }
    for (; j < cnt; j++) {
        int r = __ldg(&g_src[start + j]);
        if (act) {
            uint2 w = __ldg((const uint2*)(y + (size_t)r * H1) + lane);
            float2 f0 = __half22float2(*(const __half2*)&w.x);
            float2 f1 = __half22float2(*(const __half2*)&w.y);
            acc.x += f0.x; acc.y += f0.y; acc.z += f1.x; acc.w += f1.y;
        }
    }

    if (act) {
        float d = g_dis[node];
        float o0, o1, o2, o3;
        if (MODE == 1) {
            float4 b = *(const float4*)&bias[lane * 4];
            o0 = d * fmaxf(fmaf(d, acc.x, b.x), 0.f);
            o1 = d * fmaxf(fmaf(d, acc.y, b.y), 0.f);
            o2 = d * fmaxf(fmaf(d, acc.z, b.z), 0.f);
            o3 = d * fmaxf(fmaf(d, acc.w, b.w), 0.f);
        } else {
            o0 = d * acc.x; o1 = d * acc.y; o2 = d * acc.z; o3 = d * acc.w;
        }
        __half2 h0 = __floats2half2_rn(o0, o1);
        __half2 h1 = __floats2half2_rn(o2, o3);
        uint2 u;
        u.x = *(const unsigned*)&h0;
        u.y = *(const unsigned*)&h1;
        ((uint2*)(outh + (size_t)node * H1))[lane] = u;
    }
}

// ================= launch =================
extern "C" void kernel_launch(void* const* d_in, const int* in_sizes, int n_in,
                              void* d_out, int out_size) {
    const float* x   = (const float*)d_in[0];
    const int*   ei  = (const int*)d_in[1];
    const float* W1  = (const float*)d_in[2];
    const float* b1  = (const float*)d_in[3];
    const float* W2  = (const float*)d_in[4];
    const float* b2  = (const float*)d_in[5];
    const float* Wfc = (const float*)d_in[6];
    const float* bfc = (const float*)d_in[7];
    float*       out = (float*)d_out;

    int nN = in_sizes[0] / FIN;
    int nE = in_sizes[1] / 2;
    const int* rowI = ei;
    const int* colI = ei + nE;

    __half *p_y1h, *p_y2h, *p_s2h;
    int    *p_deg, *p_total;
    cudaGetSymbolAddress((void**)&p_y1h,  g_y1h);
    cudaGetSymbolAddress((void**)&p_y2h,  g_y2h);
    cudaGetSymbolAddress((void**)&p_s2h,  g_s2h);
    cudaGetSymbolAddress((void**)&p_deg,  g_deg);
    cudaGetSymbolAddress((void**)&p_total, g_total);

    // --- degree + CSR build (+ fused weight convert) ---
    cudaMemsetAsync(p_deg, 0, (size_t)nN * sizeof(int));
    cudaMemsetAsync(p_total, 0, sizeof(int));
    {
        int nQ  = nE / 4 + 1;                      // quad threads + tail thread
        int nQB = (nQ + 255) / 256;                // count blocks
        int nWB = (WCONV_ELEMS + 255) / 256;       // convert blocks
        k_count_conv<<<nQB + nWB, 256>>>(colI, nE, nQB, W1, W2, Wfc);
        k_assign<<<(nN + 255) / 256, 256>>>(nN);
        k_fill  <<<(nQ + 255) / 256, 256>>>(rowI, colI, nE);
    }

    // --- layer 1 (WMMA): y1h = fp16( d_r ⊙ (x @ W1) ) ---
    k_dense1_wmma<<<(nN + 63) / 64, 128>>>(x, p_y1h, nN);

    // --- agg1 + mid fused: y2h = fp16( d ⊙ relu(d ⊙ (y1_self + Σ y1[src]) + b1) ) ---
    k_gather_h<C4_H1, 1><<<(nN + 7) / 8, dim3(32, 8)>>>(p_y1h, b1, p_y2h, nN);

    // --- agg2 (commuted before GEMM): s2h = fp16( d ⊙ (y2_self + Σ y2[src]) ) ---
    k_gather_h<C4_H1, 2><<<(nN + 7) / 8, dim3(32, 8)>>>(p_y2h, nullptr, p_s2h, nN);

    // --- layer 2 + FC fused (WMMA): out = relu(s2h @ W2 + b2) @ Wfc + bfc ---
    k_dense2_fc_wmma<<<(nN + 63) / 64, 128>>>(p_s2h, b2, bfc, out, nN);
}